// round 10
// baseline (speedup 1.0000x reference)
#include <cuda_runtime.h>
#include <cuda_fp16.h>
#include <math.h>

#define BB 64
#define LCC 1024
#define LQQ 128
#define DDIM 128
#define LDH 136        // smem row stride in halfs (272B)
#define LDHC 72        // half-width slab row stride in halfs (144B)
#define LDS4 72        // k4 staging stride in floats
#define LOG2E 1.4426950408889634f

// ---- device scratch (allocation-free) ----
__device__ __half g_ch [(size_t)BB * LCC * DDIM];  // fp16(c)   (written by k2)
__device__ __half g_qwh[BB * LQQ * DDIM];          // fp16(q * w3 * log2e)
__device__ __half g_qmh[BB * LQQ * DDIM];          // fp16(q * qmf)
__device__ __half g_Eh [(size_t)BB * LCC * LQQ];   // fp16(exp(S))
__device__ __half g_Tm [BB * LQQ * DDIM];          // fp16(T * qmf)
__device__ float  g_qw2[BB * LQQ];                 // (q·w2) * log2e
__device__ float  g_z1inv[BB * LCC];
__device__ float  g_z2p[8][BB * LQQ];              // col-sum partials per i-tile

// ---- mma / ldmatrix / cp.async helpers ----
__device__ __forceinline__ unsigned sm_addr(const void* p) {
    return (unsigned)__cvta_generic_to_shared(p);
}
__device__ __forceinline__ void ldsm_x4(unsigned a, unsigned& r0, unsigned& r1,
                                        unsigned& r2, unsigned& r3) {
    asm volatile("ldmatrix.sync.aligned.m8n8.x4.shared.b16 {%0,%1,%2,%3}, [%4];"
                 : "=r"(r0), "=r"(r1), "=r"(r2), "=r"(r3) : "r"(a));
}
__device__ __forceinline__ void ldsm_x4t(unsigned a, unsigned& r0, unsigned& r1,
                                         unsigned& r2, unsigned& r3) {
    asm volatile("ldmatrix.sync.aligned.m8n8.x4.trans.shared.b16 {%0,%1,%2,%3}, [%4];"
                 : "=r"(r0), "=r"(r1), "=r"(r2), "=r"(r3) : "r"(a));
}
__device__ __forceinline__ void mma16816(float& c0, float& c1, float& c2, float& c3,
                                         unsigned a0, unsigned a1, unsigned a2, unsigned a3,
                                         unsigned b0, unsigned b1) {
    asm volatile(
        "mma.sync.aligned.m16n8k16.row.col.f32.f16.f16.f32 "
        "{%0,%1,%2,%3}, {%4,%5,%6,%7}, {%8,%9}, {%0,%1,%2,%3};"
        : "+f"(c0), "+f"(c1), "+f"(c2), "+f"(c3)
        : "r"(a0), "r"(a1), "r"(a2), "r"(a3), "r"(b0), "r"(b1));
}
__device__ __forceinline__ void cp_async16(unsigned saddr, const void* g) {
    asm volatile("cp.async.cg.shared.global [%0], [%1], 16;" :: "r"(saddr), "l"(g));
}
__device__ __forceinline__ void cp_commit() {
    asm volatile("cp.async.commit_group;");
}
template <int N> __device__ __forceinline__ void cp_wait() {
    asm volatile("cp.async.wait_group %0;" :: "n"(N));
}
__device__ __forceinline__ unsigned hmul2u(unsigned a, __half2 s) {
    __half2 r = __hmul2(*(__half2*)&a, s);
    return *(unsigned*)&r;
}

// ---------------------------------------------------------------------------
// K0: q-side prep only (8192 rows). Warp per row: qw2 fp32 dot (xlog2e),
// fp16 q*w3*log2e and q*qmf.
// ---------------------------------------------------------------------------
__global__ __launch_bounds__(256) void k0_qprep(const float* __restrict__ q_rep,
                                                const int* __restrict__ q_mask,
                                                const float* __restrict__ w) {
    int r    = (blockIdx.x * 256 + threadIdx.x) >> 5;
    int lane = threadIdx.x & 31;
    if (r >= BB * LQQ) return;
    float4 qv = *(const float4*)(q_rep + (size_t)r * DDIM + lane * 4);
    float4 w2 = *(const float4*)(w + DDIM + lane * 4);
    float4 w3 = *(const float4*)(w + 2 * DDIM + lane * 4);
    float s = qv.x * w2.x + qv.y * w2.y + qv.z * w2.z + qv.w * w2.w;
#pragma unroll
    for (int o = 16; o > 0; o >>= 1) s += __shfl_xor_sync(~0u, s, o);
    if (lane == 0) g_qw2[r] = s * LOG2E;
    __half2 a0 = __floats2half2_rn(qv.x * w3.x * LOG2E, qv.y * w3.y * LOG2E);
    __half2 a1 = __floats2half2_rn(qv.z * w3.z * LOG2E, qv.w * w3.w * LOG2E);
    uint2 u; u.x = *(unsigned*)&a0; u.y = *(unsigned*)&a1;
    *(uint2*)(g_qwh + (size_t)r * DDIM + lane * 4) = u;
    float mf = q_mask[r] ? 0.f : 1.f;
    __half2 m0 = __floats2half2_rn(qv.x * mf, qv.y * mf);
    __half2 m1 = __floats2half2_rn(qv.z * mf, qv.w * mf);
    uint2 v; v.x = *(unsigned*)&m0; v.y = *(unsigned*)&m1;
    *(uint2*)(g_qmh + (size_t)r * DDIM + lane * 4) = v;
}

// ---------------------------------------------------------------------------
// K2: loads fp32 c tile (converts -> smem + g_ch, FULL 4096 float4), computes
// cw1 in-block, S' = cw1' + qw2' + c·(q*w3*L2E)^T (log2 domain),
// E = 2^S' via ex2.f16x2. z1inv finalized, z2 partials staged.
// ---------------------------------------------------------------------------
__global__ __launch_bounds__(256) void k2_SE(const float* __restrict__ c_rep,
                                             const int* __restrict__ c_mask,
                                             const int* __restrict__ q_mask,
                                             const float* __restrict__ w) {
    int b = blockIdx.y, i0 = blockIdx.x * 128;
    extern __shared__ __half sm2[];
    __half* cw_s = sm2;                // [128][LDH]  A: rows i, cols d (fp16 c)
    __half* q_s  = sm2 + 128 * LDH;    // [128][LDH]  B: rows j, cols d
    __shared__ float z1s[128][2];
    __shared__ float z2s[128][4];
    __shared__ float qmf_s[128], cmf_s[128];
    __shared__ float cw1_s[128], qw2_s[128];
    int t = threadIdx.x, lane = t & 31, wp = t >> 5, wm = wp >> 1, wn = wp & 1;

    // phase 1a: fp32 c tile -> fp16 (smem A slab + g_ch): 4096 float4
    const float4* gc4 = (const float4*)(c_rep + ((size_t)(b * LCC + i0)) * DDIM);
    uint2* gch2 = (uint2*)(g_ch + ((size_t)(b * LCC + i0)) * DDIM);
#pragma unroll
    for (int l = 0; l < 16; l++) {
        int idx = t + l * 256;            // 0..4095 = 128 rows x 32 float4
        int row = idx >> 5, f4 = idx & 31;
        float4 v = gc4[idx];
        __half2 h0 = __floats2half2_rn(v.x, v.y);
        __half2 h1 = __floats2half2_rn(v.z, v.w);
        uint2 u; u.x = *(unsigned*)&h0; u.y = *(unsigned*)&h1;
        *(uint2*)&cw_s[row * LDH + f4 * 4] = u;
        gch2[idx] = u;
    }
    // phase 1b: q slab copy: 2048 uint4 (128 rows x 16 uint4)
    const uint4* gq = (const uint4*)(g_qwh + (size_t)b * LQQ * DDIM);
#pragma unroll
    for (int l = 0; l < 8; l++) {
        int idx = t + l * 256;            // 0..2047
        int qrow = idx >> 4, c16 = idx & 15;
        *(uint4*)&q_s[qrow * LDH + c16 * 8] = gq[idx];
    }
    // phase 2: cw1 = (c·w1)*log2e, fp32 (L1-hot re-read)
    {
        int row = t >> 1, half = t & 1;
        const float4* cr = (const float4*)(c_rep + ((size_t)(b * LCC + i0 + row)) * DDIM + half * 64);
        const float4* w4 = (const float4*)(w + half * 64);
        float s = 0.f;
#pragma unroll
        for (int k = 0; k < 16; k++) {
            float4 a = cr[k], ww = w4[k];
            s += a.x * ww.x + a.y * ww.y + a.z * ww.z + a.w * ww.w;
        }
        s += __shfl_xor_sync(~0u, s, 1);
        if (half == 0) cw1_s[row] = s * LOG2E;
    }
    if (t < 128) {
        qmf_s[t] = q_mask[b * LQQ + t] ? 0.f : 1.f;
        cmf_s[t] = c_mask[b * LCC + i0 + t] ? 0.f : 1.f;
        qw2_s[t] = g_qw2[b * LQQ + t];
    }
    __syncthreads();

    float acc[2][8][4];
#pragma unroll
    for (int a = 0; a < 2; a++)
#pragma unroll
        for (int c = 0; c < 8; c++)
#pragma unroll
            for (int k = 0; k < 4; k++) acc[a][c][k] = 0.f;

    unsigned aB = sm_addr(&cw_s[(wm * 32 + (lane & 15)) * LDH + 8 * (lane >> 4)]);
    unsigned bB = sm_addr(&q_s[(wn * 64 + 8 * ((lane >> 4) & 1) + (lane & 7)) * LDH
                               + 8 * ((lane >> 3) & 1)]);
#pragma unroll
    for (int ks = 0; ks < 8; ks++) {
        unsigned A[2][4];
        ldsm_x4(aB + ks * 32,                 A[0][0], A[0][1], A[0][2], A[0][3]);
        ldsm_x4(aB + 16 * LDH * 2 + ks * 32,  A[1][0], A[1][1], A[1][2], A[1][3]);
        unsigned Bf[8][2];
#pragma unroll
        for (int np = 0; np < 4; np++) {
            unsigned r0, r1, r2, r3;
            ldsm_x4(bB + np * (16 * LDH * 2) + ks * 32, r0, r1, r2, r3);
            Bf[2 * np][0] = r0; Bf[2 * np][1] = r1;
            Bf[2 * np + 1][0] = r2; Bf[2 * np + 1][1] = r3;
        }
#pragma unroll
        for (int a = 0; a < 2; a++)
#pragma unroll
            for (int c = 0; c < 8; c++)
                mma16816(acc[a][c][0], acc[a][c][1], acc[a][c][2], acc[a][c][3],
                         A[a][0], A[a][1], A[a][2], A[a][3], Bf[c][0], Bf[c][1]);
    }

    // epilogue: add rank-1 terms (log2 domain), ex2.f16x2, store E, z1/z2
    int g = lane >> 2, q4 = lane & 3;
    float z1a[2][2] = {{0.f, 0.f}, {0.f, 0.f}};
    float z2a[8][2];
#pragma unroll
    for (int c = 0; c < 8; c++) { z2a[c][0] = 0.f; z2a[c][1] = 0.f; }
#pragma unroll
    for (int a = 0; a < 2; a++) {
        int lr0 = wm * 32 + a * 16 + g;
        float cwv0 = cw1_s[lr0], cwv1 = cw1_s[lr0 + 8];
        float cmf0 = cmf_s[lr0], cmf1 = cmf_s[lr0 + 8];
        __half* e0p = g_Eh + ((size_t)(b * LCC + i0 + lr0)) * LQQ;
        __half* e1p = e0p + 8 * LQQ;
#pragma unroll
        for (int c = 0; c < 8; c++) {
            int col = wn * 64 + c * 8 + 2 * q4;
            float qw0 = qw2_s[col], qw1 = qw2_s[col + 1];
            float qf0 = qmf_s[col], qf1 = qmf_s[col + 1];
            __half2 p01 = __floats2half2_rn(acc[a][c][0] + cwv0 + qw0,
                                            acc[a][c][1] + cwv0 + qw1);
            __half2 p23 = __floats2half2_rn(acc[a][c][2] + cwv1 + qw0,
                                            acc[a][c][3] + cwv1 + qw1);
            __half2 e01 = h2exp2(p01);
            __half2 e23 = h2exp2(p23);
            *(__half2*)(e0p + col) = e01;
            *(__half2*)(e1p + col) = e23;
            float2 f01 = __half22float2(e01);
            float2 f23 = __half22float2(e23);
            z1a[a][0] += qf0 * f01.x + qf1 * f01.y;
            z1a[a][1] += qf0 * f23.x + qf1 * f23.y;
            z2a[c][0] += cmf0 * f01.x + cmf1 * f23.x;
            z2a[c][1] += cmf0 * f01.y + cmf1 * f23.y;
        }
    }
#pragma unroll
    for (int a = 0; a < 2; a++)
#pragma unroll
        for (int h = 0; h < 2; h++) {
            float v = z1a[a][h];
            v += __shfl_xor_sync(~0u, v, 1);
            v += __shfl_xor_sync(~0u, v, 2);
            if (q4 == 0) z1s[wm * 32 + a * 16 + g + 8 * h][wn] = v;
        }
#pragma unroll
    for (int c = 0; c < 8; c++)
#pragma unroll
        for (int s = 0; s < 2; s++) {
            float v = z2a[c][s];
            v += __shfl_xor_sync(~0u, v, 4);
            v += __shfl_xor_sync(~0u, v, 8);
            v += __shfl_xor_sync(~0u, v, 16);
            if (g == 0) z2s[wn * 64 + c * 8 + 2 * q4 + s][wm] = v;
        }
    __syncthreads();
    if (t < 128) {
        g_z1inv[b * LCC + i0 + t] = 1.f / (z1s[t][0] + z1s[t][1]);
        g_z2p[blockIdx.x][b * LQQ + t] = z2s[t][0] + z2s[t][1] + z2s[t][2] + z2s[t][3];
    }
}

// ---------------------------------------------------------------------------
// K3: T[j,d] = qmf[j]/z2[j] * sum_i cmf[i]*E[i,j]*c[i,d]  -> fp16 g_Tm
// N-split over d halves: grid (2, BB). M=128 j, N=64 d, K=1024 i.
// ---------------------------------------------------------------------------
#define EBUFB (64 * LDH * 2)    // bytes per E buffer
#define CBUFB (64 * LDHC * 2)   // bytes per c buffer
__global__ __launch_bounds__(256) void k3_T(const int* __restrict__ c_mask,
                                            const int* __restrict__ q_mask) {
    int b = blockIdx.y, d0 = blockIdx.x * 64;
    extern __shared__ __half s3[];
    __half* E_s   = s3;                         // 2 x 64 x LDH
    __half* c_s   = s3 + 2 * 64 * LDH;          // 2 x 64 x LDHC
    __half* cmf_s = s3 + 2 * 64 * LDH + 2 * 64 * LDHC;  // 1024
    float*  f_s   = (float*)(cmf_s + 1024);     // 128
    int t = threadIdx.x, lane = t & 31, wp = t >> 5, wm = wp >> 1, wn = wp & 1;

    unsigned Ebase = sm_addr(E_s);
    unsigned Cbase = sm_addr(c_s);
    {
        const char* gE = (const char*)(g_Eh + ((size_t)b * LCC) * LQQ);
        const char* gC = (const char*)(g_ch + ((size_t)b * LCC) * DDIM + d0);
#pragma unroll
        for (int l = 0; l < 4; l++) {
            int u = t + l * 256, row = u >> 4, c16 = u & 15;
            cp_async16(Ebase + (row * LDH + c16 * 8) * 2, gE + ((size_t)row * LQQ + c16 * 8) * 2);
        }
#pragma unroll
        for (int l = 0; l < 2; l++) {
            int u = t + l * 256, row = u >> 3, c8 = u & 7;
            cp_async16(Cbase + (row * LDHC + c8 * 8) * 2, gC + ((size_t)row * DDIM + c8 * 8) * 2);
        }
        cp_commit();
    }
#pragma unroll
    for (int l = 0; l < 4; l++) {
        int i = t + l * 256;
        cmf_s[i] = __float2half(c_mask[b * LCC + i] ? 0.f : 1.f);
    }
    if (t < 128) {
        float z2 = 0.f;
#pragma unroll
        for (int s = 0; s < 8; s++) z2 += g_z2p[s][b * LQQ + t];
        f_s[t] = q_mask[b * LQQ + t] ? 0.f : (1.f / z2);
    }

    float acc[2][4][4];
#pragma unroll
    for (int a = 0; a < 2; a++)
#pragma unroll
        for (int c = 0; c < 4; c++)
#pragma unroll
            for (int k = 0; k < 4; k++) acc[a][c][k] = 0.f;

    unsigned aB = Ebase + (((lane & 7) + 8 * ((lane >> 4) & 1)) * LDH
                           + wm * 32 + 8 * ((lane >> 3) & 1)) * 2;
    unsigned bB = Cbase + (((lane & 7) + 8 * ((lane >> 3) & 1)) * LDHC
                           + wn * 32 + 8 * ((lane >> 4) & 1)) * 2;

    for (int kc = 0; kc < 16; kc++) {
        int buf = kc & 1;
        if (kc + 1 < 16) {
            int nxt = buf ^ 1;
            const char* gE = (const char*)(g_Eh + ((size_t)(b * LCC + (kc + 1) * 64)) * LQQ);
            const char* gC = (const char*)(g_ch + ((size_t)(b * LCC + (kc + 1) * 64)) * DDIM + d0);
#pragma unroll
            for (int l = 0; l < 4; l++) {
                int u = t + l * 256, row = u >> 4, c16 = u & 15;
                cp_async16(Ebase + nxt * EBUFB + (row * LDH + c16 * 8) * 2,
                           gE + ((size_t)row * LQQ + c16 * 8) * 2);
            }
#pragma unroll
            for (int l = 0; l < 2; l++) {
                int u = t + l * 256, row = u >> 3, c8 = u & 7;
                cp_async16(Cbase + nxt * CBUFB + (row * LDHC + c8 * 8) * 2,
                           gC + ((size_t)row * DDIM + c8 * 8) * 2);
            }
            cp_commit();
            cp_wait<1>();
        } else {
            cp_wait<0>();
        }
        __syncthreads();
#pragma unroll
        for (int ks = 0; ks < 4; ks++) {
            int ibase = kc * 64 + ks * 16;
            __half2 cm_lo = *(__half2*)&cmf_s[ibase + (lane & 3) * 2];
            __half2 cm_hi = *(__half2*)&cmf_s[ibase + 8 + (lane & 3) * 2];
            unsigned A[2][4];
            ldsm_x4t(aB + buf * EBUFB + ks * (16 * LDH * 2),      A[0][0], A[0][1], A[0][2], A[0][3]);
            ldsm_x4t(aB + buf * EBUFB + ks * (16 * LDH * 2) + 32, A[1][0], A[1][1], A[1][2], A[1][3]);
#pragma unroll
            for (int a = 0; a < 2; a++) {
                A[a][0] = hmul2u(A[a][0], cm_lo);
                A[a][1] = hmul2u(A[a][1], cm_lo);
                A[a][2] = hmul2u(A[a][2], cm_hi);
                A[a][3] = hmul2u(A[a][3], cm_hi);
            }
            unsigned Bf[4][2];
#pragma unroll
            for (int np = 0; np < 2; np++) {
                unsigned r0, r1, r2, r3;
                ldsm_x4t(bB + buf * CBUFB + ks * (16 * LDHC * 2) + np * 32, r0, r1, r2, r3);
                Bf[2 * np][0] = r0; Bf[2 * np][1] = r1;
                Bf[2 * np + 1][0] = r2; Bf[2 * np + 1][1] = r3;
            }
#pragma unroll
            for (int a = 0; a < 2; a++)
#pragma unroll
                for (int c = 0; c < 4; c++)
                    mma16816(acc[a][c][0], acc[a][c][1], acc[a][c][2], acc[a][c][3],
                             A[a][0], A[a][1], A[a][2], A[a][3], Bf[c][0], Bf[c][1]);
        }
        __syncthreads();
    }

    int g = lane >> 2, q4 = lane & 3;
#pragma unroll
    for (int a = 0; a < 2; a++) {
        int j0 = wm * 32 + a * 16 + g;
        float f0 = f_s[j0], f1 = f_s[j0 + 8];
        __half* o0 = g_Tm + ((size_t)(b * LQQ + j0)) * DDIM + d0;
        __half* o1 = o0 + 8 * DDIM;
#pragma unroll
        for (int c = 0; c < 4; c++) {
            int col = wn * 32 + c * 8 + 2 * q4;
            *(__half2*)(o0 + col) = __floats2half2_rn(acc[a][c][0] * f0, acc[a][c][1] * f0);
            *(__half2*)(o1 + col) = __floats2half2_rn(acc[a][c][2] * f1, acc[a][c][3] * f1);
        }
    }
}

// ---------------------------------------------------------------------------
// K4: fused dual GEMM A = (E·qmh)/z1, Batt = (E·Tm)/z1; parallel smem-staged
// epilogue, fully-coalesced float4 stores of [c, A, c*A, c*Batt].
// Grid (32, BB): bx&1 = d-half, bx>>1 = i-tile of 64. M=64 i, N=64 d, K=128 j.
// 4 CTAs/SM target (reg cap 64).
// ---------------------------------------------------------------------------
__global__ __launch_bounds__(256, 4) void k4_out(const float* __restrict__ c_rep,
                                                 float* __restrict__ out) {
    int b = blockIdx.y;
    int i0 = (blockIdx.x >> 1) * 64;
    int d0 = (blockIdx.x & 1) * 64;
    extern __shared__ __half sm4[];
    __half* E_s = sm4;                   // [64][LDH]    rows i, cols j (A)
    __half* q_s = sm4 + 64 * LDH;        // [128][LDHC]  rows j, d-half (B)
    __half* t_s = q_s + 128 * LDHC;      // [128][LDHC]  rows j, d-half (B)
    float* Asm = (float*)sm4;            // staging (reused post-MMA): [64][LDS4]
    float* Bsm = Asm + 64 * LDS4;
    int t = threadIdx.x, lane = t & 31, wp = t >> 5, wm = wp >> 1, wn = wp & 1;
    const uint4* gE = (const uint4*)(g_Eh + ((size_t)(b * LCC + i0)) * LQQ);
    const __half* gQ = g_qmh + (size_t)b * LQQ * DDIM + d0;
    const __half* gT = g_Tm + (size_t)b * LQQ * DDIM + d0;
#pragma unroll
    for (int l = 0; l < 4; l++) {
        int u = t + l * 256, row = u >> 4, c16 = u & 15;
        *(uint4*)&E_s[row * LDH + c16 * 8] = gE[u];
    }
#pragma unroll
    for (int l = 0; l < 4; l++) {
        int u = t + l * 256, row = u >> 3, c8 = u & 7;
        *(uint4*)&q_s[row * LDHC + c8 * 8] = *(const uint4*)(gQ + (size_t)row * DDIM + c8 * 8);
        *(uint4*)&t_s[row * LDHC + c8 * 8] = *(const uint4*)(gT + (size_t)row * DDIM + c8 * 8);
    }
    __syncthreads();

    float accA[4][4], accB[4][4];
#pragma unroll
    for (int c = 0; c < 4; c++)
#pragma unroll
        for (int k = 0; k < 4; k++) { accA[c][k] = 0.f; accB[c][k] = 0.f; }

    unsigned aB = sm_addr(&E_s[(wm * 16 + (lane & 15)) * LDH + 8 * (lane >> 4)]);
    unsigned qB = sm_addr(&q_s[((lane & 7) + 8 * ((lane >> 3) & 1)) * LDHC
                               + wn * 32 + 8 * ((lane >> 4) & 1)]);
    unsigned tB = sm_addr(&t_s[((lane & 7) + 8 * ((lane >> 3) & 1)) * LDHC
                               + wn * 32 + 8 * ((lane >> 4) & 1)]);
#pragma unroll
    for (int ks = 0; ks < 8; ks++) {
        unsigned A0, A1, A2, A3;
        ldsm_x4(aB + ks * 32, A0, A1, A2, A3);
#pragma unroll
        for (int np = 0; np < 2; np++) {
            unsigned r0, r1, r2, r3;
            ldsm_x4t(qB + ks * (16 * LDHC * 2) + np * 32, r0, r1, r2, r3);
            mma16816(accA[2 * np][0], accA[2 * np][1], accA[2 * np][2], accA[2 * np][3],
                     A0, A1, A2, A3, r0, r1);
            mma16816(accA[2 * np + 1][0], accA[2 * np + 1][1], accA[2 * np + 1][2], accA[2 * np + 1][3],
                     A0, A1, A2, A3, r2, r3);
            ldsm_x4t(tB + ks * (16 * LDHC * 2) + np * 32, r0, r1, r2, r3);
            mma16816(accB[2 * np][0], accB[2 * np][1], accB[2 * np][2], accB[2 * np][3],
                     A0, A1, A2, A3, r0, r1);
            mma16816(accB[2 * np + 1][0], accB[2 * np + 1][1], accB[2 * np + 1][2], accB[2 * np + 1][3],
                     A0, A1, A2, A3, r2, r3);
        }
    }

    int g = lane >> 2, q4 = lane & 3;
    float z0, z1v;
    {
        size_t gr = (size_t)(b * LCC + i0 + wm * 16 + g);
        z0 = g_z1inv[gr];
        z1v = g_z1inv[gr + 8];
    }
    __syncthreads();   // all warps done reading E_s/q_s/t_s; smem reused below

    // all-warp parallel staging of 64 rows
    {
        int r0 = wm * 16 + g, r1 = r0 + 8;
#pragma unroll
        for (int c = 0; c < 4; c++) {
            int col = wn * 32 + c * 8 + 2 * q4;
            *(float2*)&Asm[r0 * LDS4 + col] = make_float2(accA[c][0] * z0, accA[c][1] * z0);
            *(float2*)&Asm[r1 * LDS4 + col] = make_float2(accA[c][2] * z1v, accA[c][3] * z1v);
            *(float2*)&Bsm[r0 * LDS4 + col] = make_float2(accB[c][0] * z0, accB[c][1] * z0);
            *(float2*)&Bsm[r1 * LDS4 + col] = make_float2(accB[c][2] * z1v, accB[c][3] * z1v);
        }
    }
    __syncthreads();

    // dense float4 stores: 64 rows x 64 cols, 4 iterations
#pragma unroll
    for (int it = 0; it < 4; it++) {
        int u = t + it * 256;
        int row = u >> 4, col = (u & 15) * 4;
        size_t gr = (size_t)(b * LCC + i0 + row);
        float4 c4 = *(const float4*)(c_rep + gr * DDIM + d0 + col);
        float4 a4 = *(const float4*)&Asm[row * LDS4 + col];
        float4 b4 = *(const float4*)&Bsm[row * LDS4 + col];
        float* ob = out + gr * (4 * DDIM) + d0 + col;
        *(float4*)ob = c4;
        *(float4*)(ob + DDIM) = a4;
        *(float4*)(ob + 2 * DDIM) = make_float4(c4.x * a4.x, c4.y * a4.y, c4.z * a4.z, c4.w * a4.w);
        *(float4*)(ob + 3 * DDIM) = make_float4(c4.x * b4.x, c4.y * b4.y, c4.z * b4.z, c4.w * b4.w);
    }
}

// ---------------------------------------------------------------------------
extern "C" void kernel_launch(void* const* d_in, const int* in_sizes, int n_in,
                              void* d_out, int out_size) {
    const float* c_rep  = (const float*)d_in[0];
    const float* q_rep  = (const float*)d_in[1];
    const int*   c_mask = (const int*)d_in[2];
    const int*   q_mask = (const int*)d_in[3];
    const float* w      = (const float*)d_in[4];
    float* out = (float*)d_out;

    k0_qprep<<<(BB * LQQ) / 8, 256>>>(q_rep, q_mask, w);
    {
        int smem = 2 * 128 * LDH * 2;  // 69632
        cudaFuncSetAttribute(k2_SE, cudaFuncAttributeMaxDynamicSharedMemorySize, smem);
        dim3 gr(8, BB);
        k2_SE<<<gr, 256, smem>>>(c_rep, c_mask, q_mask, w);
    }
    {
        int smem = 2 * EBUFB + 2 * CBUFB + 1024 * 2 + 128 * 4;  // 55808
        cudaFuncSetAttribute(k3_T, cudaFuncAttributeMaxDynamicSharedMemorySize, smem);
        dim3 gr(2, BB);
        k3_T<<<gr, 256, smem>>>(c_mask, q_mask);
    }
    {
        int smem = (64 * LDH + 2 * 128 * LDHC) * 2;  // 54272 (>= staging 36864)
        cudaFuncSetAttribute(k4_out, cudaFuncAttributeMaxDynamicSharedMemorySize, smem);
        dim3 gr(32, BB);
        k4_out<<<gr, 256, smem>>>(c_rep, out);
    }
}

// round 11
// speedup vs baseline: 1.1292x; 1.1292x over previous
#include <cuda_runtime.h>
#include <cuda_fp16.h>
#include <math.h>

#define BB 64
#define LCC 1024
#define LQQ 128
#define DDIM 128
#define LDH 136        // smem row stride in halfs (272B)
#define LDHC 72        // half-width slab row stride in halfs (144B)
#define LDS4 72        // k4 staging stride in floats
#define LOG2E 1.4426950408889634f

// ---- device scratch (allocation-free) ----
__device__ __half g_ch [(size_t)BB * LCC * DDIM];  // fp16(c)   (written by k2)
__device__ __half g_qwh[BB * LQQ * DDIM];          // fp16(q * w3 * log2e)
__device__ __half g_qmh[BB * LQQ * DDIM];          // fp16(q * qmf)
__device__ __half g_Eh [(size_t)BB * LCC * LQQ];   // fp16(exp(S))
__device__ __half g_Tm [BB * LQQ * DDIM];          // fp16(T * qmf)
__device__ float  g_qw2[BB * LQQ];                 // (q·w2) * log2e
__device__ float  g_z1inv[BB * LCC];
__device__ float  g_z2p[8][BB * LQQ];              // col-sum partials per i-tile

// ---- mma / ldmatrix / cp.async helpers ----
__device__ __forceinline__ unsigned sm_addr(const void* p) {
    return (unsigned)__cvta_generic_to_shared(p);
}
__device__ __forceinline__ void ldsm_x4(unsigned a, unsigned& r0, unsigned& r1,
                                        unsigned& r2, unsigned& r3) {
    asm volatile("ldmatrix.sync.aligned.m8n8.x4.shared.b16 {%0,%1,%2,%3}, [%4];"
                 : "=r"(r0), "=r"(r1), "=r"(r2), "=r"(r3) : "r"(a));
}
__device__ __forceinline__ void ldsm_x4t(unsigned a, unsigned& r0, unsigned& r1,
                                         unsigned& r2, unsigned& r3) {
    asm volatile("ldmatrix.sync.aligned.m8n8.x4.trans.shared.b16 {%0,%1,%2,%3}, [%4];"
                 : "=r"(r0), "=r"(r1), "=r"(r2), "=r"(r3) : "r"(a));
}
__device__ __forceinline__ void mma16816(float& c0, float& c1, float& c2, float& c3,
                                         unsigned a0, unsigned a1, unsigned a2, unsigned a3,
                                         unsigned b0, unsigned b1) {
    asm volatile(
        "mma.sync.aligned.m16n8k16.row.col.f32.f16.f16.f32 "
        "{%0,%1,%2,%3}, {%4,%5,%6,%7}, {%8,%9}, {%0,%1,%2,%3};"
        : "+f"(c0), "+f"(c1), "+f"(c2), "+f"(c3)
        : "r"(a0), "r"(a1), "r"(a2), "r"(a3), "r"(b0), "r"(b1));
}
__device__ __forceinline__ void cp_async16(unsigned saddr, const void* g) {
    asm volatile("cp.async.cg.shared.global [%0], [%1], 16;" :: "r"(saddr), "l"(g));
}
__device__ __forceinline__ void cp_commit() {
    asm volatile("cp.async.commit_group;");
}
template <int N> __device__ __forceinline__ void cp_wait() {
    asm volatile("cp.async.wait_group %0;" :: "n"(N));
}
__device__ __forceinline__ unsigned hmul2u(unsigned a, __half2 s) {
    __half2 r = __hmul2(*(__half2*)&a, s);
    return *(unsigned*)&r;
}

// ---------------------------------------------------------------------------
// K0: q-side prep only (8192 rows). Warp per row: qw2 fp32 dot (xlog2e),
// fp16 q*w3*log2e and q*qmf.
// ---------------------------------------------------------------------------
__global__ __launch_bounds__(256) void k0_qprep(const float* __restrict__ q_rep,
                                                const int* __restrict__ q_mask,
                                                const float* __restrict__ w) {
    int r    = (blockIdx.x * 256 + threadIdx.x) >> 5;
    int lane = threadIdx.x & 31;
    if (r >= BB * LQQ) return;
    float4 qv = *(const float4*)(q_rep + (size_t)r * DDIM + lane * 4);
    float4 w2 = *(const float4*)(w + DDIM + lane * 4);
    float4 w3 = *(const float4*)(w + 2 * DDIM + lane * 4);
    float s = qv.x * w2.x + qv.y * w2.y + qv.z * w2.z + qv.w * w2.w;
#pragma unroll
    for (int o = 16; o > 0; o >>= 1) s += __shfl_xor_sync(~0u, s, o);
    if (lane == 0) g_qw2[r] = s * LOG2E;
    __half2 a0 = __floats2half2_rn(qv.x * w3.x * LOG2E, qv.y * w3.y * LOG2E);
    __half2 a1 = __floats2half2_rn(qv.z * w3.z * LOG2E, qv.w * w3.w * LOG2E);
    uint2 u; u.x = *(unsigned*)&a0; u.y = *(unsigned*)&a1;
    *(uint2*)(g_qwh + (size_t)r * DDIM + lane * 4) = u;
    float mf = q_mask[r] ? 0.f : 1.f;
    __half2 m0 = __floats2half2_rn(qv.x * mf, qv.y * mf);
    __half2 m1 = __floats2half2_rn(qv.z * mf, qv.w * mf);
    uint2 v; v.x = *(unsigned*)&m0; v.y = *(unsigned*)&m1;
    *(uint2*)(g_qmh + (size_t)r * DDIM + lane * 4) = v;
}

// ---------------------------------------------------------------------------
// K2: loads fp32 c tile (convert -> smem + g_ch) with cw1 computed IN-REGISTER
// during the convert loop (warp w holds row w+8l at iter l; lane = d-chunk).
// S' = cw1' + qw2' + c·(q*w3*L2E)^T (log2 domain), E = 2^S' via ex2.f16x2.
// z1inv finalized, z2 partials staged.
// ---------------------------------------------------------------------------
__global__ __launch_bounds__(256) void k2_SE(const float* __restrict__ c_rep,
                                             const int* __restrict__ c_mask,
                                             const int* __restrict__ q_mask,
                                             const float* __restrict__ w) {
    int b = blockIdx.y, i0 = blockIdx.x * 128;
    extern __shared__ __half sm2[];
    __half* cw_s = sm2;                // [128][LDH]  A: rows i, cols d (fp16 c)
    __half* q_s  = sm2 + 128 * LDH;    // [128][LDH]  B: rows j, cols d
    __shared__ float z1s[128][2];
    __shared__ float z2s[128][4];
    __shared__ float qmf_s[128], cmf_s[128];
    __shared__ float cw1_s[128], qw2_s[128];
    int t = threadIdx.x, lane = t & 31, wp = t >> 5, wm = wp >> 1, wn = wp & 1;

    // phase 1a: fp32 c tile -> fp16 (smem + g_ch); cw1 from registers.
    // idx = t + l*256: row = idx>>5 = wp + 8*l, chunk f4 = idx&31 = lane.
    const float4* gc4 = (const float4*)(c_rep + ((size_t)(b * LCC + i0)) * DDIM);
    uint2* gch2 = (uint2*)(g_ch + ((size_t)(b * LCC + i0)) * DDIM);
    float4 w1c = *(const float4*)(w + lane * 4);
#pragma unroll
    for (int l = 0; l < 16; l++) {
        int idx = t + l * 256;            // 0..4095 = 128 rows x 32 float4
        int row = wp + 8 * l;
        float4 v = gc4[idx];
        __half2 h0 = __floats2half2_rn(v.x, v.y);
        __half2 h1 = __floats2half2_rn(v.z, v.w);
        uint2 u; u.x = *(unsigned*)&h0; u.y = *(unsigned*)&h1;
        *(uint2*)&cw_s[row * LDH + lane * 4] = u;
        gch2[idx] = u;
        float s = v.x * w1c.x + v.y * w1c.y + v.z * w1c.z + v.w * w1c.w;
#pragma unroll
        for (int o = 16; o > 0; o >>= 1) s += __shfl_xor_sync(~0u, s, o);
        if (lane == 0) cw1_s[row] = s * LOG2E;
    }
    // phase 1b: q slab copy: 2048 uint4 (128 rows x 16 uint4)
    const uint4* gq = (const uint4*)(g_qwh + (size_t)b * LQQ * DDIM);
#pragma unroll
    for (int l = 0; l < 8; l++) {
        int idx = t + l * 256;            // 0..2047
        int qrow = idx >> 4, c16 = idx & 15;
        *(uint4*)&q_s[qrow * LDH + c16 * 8] = gq[idx];
    }
    if (t < 128) {
        qmf_s[t] = q_mask[b * LQQ + t] ? 0.f : 1.f;
        cmf_s[t] = c_mask[b * LCC + i0 + t] ? 0.f : 1.f;
        qw2_s[t] = g_qw2[b * LQQ + t];
    }
    __syncthreads();

    float acc[2][8][4];
#pragma unroll
    for (int a = 0; a < 2; a++)
#pragma unroll
        for (int c = 0; c < 8; c++)
#pragma unroll
            for (int k = 0; k < 4; k++) acc[a][c][k] = 0.f;

    unsigned aB = sm_addr(&cw_s[(wm * 32 + (lane & 15)) * LDH + 8 * (lane >> 4)]);
    unsigned bB = sm_addr(&q_s[(wn * 64 + 8 * ((lane >> 4) & 1) + (lane & 7)) * LDH
                               + 8 * ((lane >> 3) & 1)]);
#pragma unroll
    for (int ks = 0; ks < 8; ks++) {
        unsigned A[2][4];
        ldsm_x4(aB + ks * 32,                 A[0][0], A[0][1], A[0][2], A[0][3]);
        ldsm_x4(aB + 16 * LDH * 2 + ks * 32,  A[1][0], A[1][1], A[1][2], A[1][3]);
        unsigned Bf[8][2];
#pragma unroll
        for (int np = 0; np < 4; np++) {
            unsigned r0, r1, r2, r3;
            ldsm_x4(bB + np * (16 * LDH * 2) + ks * 32, r0, r1, r2, r3);
            Bf[2 * np][0] = r0; Bf[2 * np][1] = r1;
            Bf[2 * np + 1][0] = r2; Bf[2 * np + 1][1] = r3;
        }
#pragma unroll
        for (int a = 0; a < 2; a++)
#pragma unroll
            for (int c = 0; c < 8; c++)
                mma16816(acc[a][c][0], acc[a][c][1], acc[a][c][2], acc[a][c][3],
                         A[a][0], A[a][1], A[a][2], A[a][3], Bf[c][0], Bf[c][1]);
    }

    // epilogue: add rank-1 terms (log2 domain), ex2.f16x2, store E, z1/z2
    int g = lane >> 2, q4 = lane & 3;
    float z1a[2][2] = {{0.f, 0.f}, {0.f, 0.f}};
    float z2a[8][2];
#pragma unroll
    for (int c = 0; c < 8; c++) { z2a[c][0] = 0.f; z2a[c][1] = 0.f; }
#pragma unroll
    for (int a = 0; a < 2; a++) {
        int lr0 = wm * 32 + a * 16 + g;
        float cwv0 = cw1_s[lr0], cwv1 = cw1_s[lr0 + 8];
        float cmf0 = cmf_s[lr0], cmf1 = cmf_s[lr0 + 8];
        __half* e0p = g_Eh + ((size_t)(b * LCC + i0 + lr0)) * LQQ;
        __half* e1p = e0p + 8 * LQQ;
#pragma unroll
        for (int c = 0; c < 8; c++) {
            int col = wn * 64 + c * 8 + 2 * q4;
            float qw0 = qw2_s[col], qw1 = qw2_s[col + 1];
            float qf0 = qmf_s[col], qf1 = qmf_s[col + 1];
            __half2 p01 = __floats2half2_rn(acc[a][c][0] + cwv0 + qw0,
                                            acc[a][c][1] + cwv0 + qw1);
            __half2 p23 = __floats2half2_rn(acc[a][c][2] + cwv1 + qw0,
                                            acc[a][c][3] + cwv1 + qw1);
            __half2 e01 = h2exp2(p01);
            __half2 e23 = h2exp2(p23);
            *(__half2*)(e0p + col) = e01;
            *(__half2*)(e1p + col) = e23;
            float2 f01 = __half22float2(e01);
            float2 f23 = __half22float2(e23);
            z1a[a][0] += qf0 * f01.x + qf1 * f01.y;
            z1a[a][1] += qf0 * f23.x + qf1 * f23.y;
            z2a[c][0] += cmf0 * f01.x + cmf1 * f23.x;
            z2a[c][1] += cmf0 * f01.y + cmf1 * f23.y;
        }
    }
#pragma unroll
    for (int a = 0; a < 2; a++)
#pragma unroll
        for (int h = 0; h < 2; h++) {
            float v = z1a[a][h];
            v += __shfl_xor_sync(~0u, v, 1);
            v += __shfl_xor_sync(~0u, v, 2);
            if (q4 == 0) z1s[wm * 32 + a * 16 + g + 8 * h][wn] = v;
        }
#pragma unroll
    for (int c = 0; c < 8; c++)
#pragma unroll
        for (int s = 0; s < 2; s++) {
            float v = z2a[c][s];
            v += __shfl_xor_sync(~0u, v, 4);
            v += __shfl_xor_sync(~0u, v, 8);
            v += __shfl_xor_sync(~0u, v, 16);
            if (g == 0) z2s[wn * 64 + c * 8 + 2 * q4 + s][wm] = v;
        }
    __syncthreads();
    if (t < 128) {
        g_z1inv[b * LCC + i0 + t] = 1.f / (z1s[t][0] + z1s[t][1]);
        g_z2p[blockIdx.x][b * LQQ + t] = z2s[t][0] + z2s[t][1] + z2s[t][2] + z2s[t][3];
    }
}

// ---------------------------------------------------------------------------
// K3: T[j,d] = qmf[j]/z2[j] * sum_i cmf[i]*E[i,j]*c[i,d]  -> fp16 g_Tm
// N-split over d halves: grid (2, BB). M=128 j, N=64 d, K=1024 i.
// ---------------------------------------------------------------------------
#define EBUFB (64 * LDH * 2)    // bytes per E buffer
#define CBUFB (64 * LDHC * 2)   // bytes per c buffer
__global__ __launch_bounds__(256) void k3_T(const int* __restrict__ c_mask,
                                            const int* __restrict__ q_mask) {
    int b = blockIdx.y, d0 = blockIdx.x * 64;
    extern __shared__ __half s3[];
    __half* E_s   = s3;                         // 2 x 64 x LDH
    __half* c_s   = s3 + 2 * 64 * LDH;          // 2 x 64 x LDHC
    __half* cmf_s = s3 + 2 * 64 * LDH + 2 * 64 * LDHC;  // 1024
    float*  f_s   = (float*)(cmf_s + 1024);     // 128
    int t = threadIdx.x, lane = t & 31, wp = t >> 5, wm = wp >> 1, wn = wp & 1;

    unsigned Ebase = sm_addr(E_s);
    unsigned Cbase = sm_addr(c_s);
    {
        const char* gE = (const char*)(g_Eh + ((size_t)b * LCC) * LQQ);
        const char* gC = (const char*)(g_ch + ((size_t)b * LCC) * DDIM + d0);
#pragma unroll
        for (int l = 0; l < 4; l++) {
            int u = t + l * 256, row = u >> 4, c16 = u & 15;
            cp_async16(Ebase + (row * LDH + c16 * 8) * 2, gE + ((size_t)row * LQQ + c16 * 8) * 2);
        }
#pragma unroll
        for (int l = 0; l < 2; l++) {
            int u = t + l * 256, row = u >> 3, c8 = u & 7;
            cp_async16(Cbase + (row * LDHC + c8 * 8) * 2, gC + ((size_t)row * DDIM + c8 * 8) * 2);
        }
        cp_commit();
    }
#pragma unroll
    for (int l = 0; l < 4; l++) {
        int i = t + l * 256;
        cmf_s[i] = __float2half(c_mask[b * LCC + i] ? 0.f : 1.f);
    }
    if (t < 128) {
        float z2 = 0.f;
#pragma unroll
        for (int s = 0; s < 8; s++) z2 += g_z2p[s][b * LQQ + t];
        f_s[t] = q_mask[b * LQQ + t] ? 0.f : (1.f / z2);
    }

    float acc[2][4][4];
#pragma unroll
    for (int a = 0; a < 2; a++)
#pragma unroll
        for (int c = 0; c < 4; c++)
#pragma unroll
            for (int k = 0; k < 4; k++) acc[a][c][k] = 0.f;

    unsigned aB = Ebase + (((lane & 7) + 8 * ((lane >> 4) & 1)) * LDH
                           + wm * 32 + 8 * ((lane >> 3) & 1)) * 2;
    unsigned bB = Cbase + (((lane & 7) + 8 * ((lane >> 3) & 1)) * LDHC
                           + wn * 32 + 8 * ((lane >> 4) & 1)) * 2;

    for (int kc = 0; kc < 16; kc++) {
        int buf = kc & 1;
        if (kc + 1 < 16) {
            int nxt = buf ^ 1;
            const char* gE = (const char*)(g_Eh + ((size_t)(b * LCC + (kc + 1) * 64)) * LQQ);
            const char* gC = (const char*)(g_ch + ((size_t)(b * LCC + (kc + 1) * 64)) * DDIM + d0);
#pragma unroll
            for (int l = 0; l < 4; l++) {
                int u = t + l * 256, row = u >> 4, c16 = u & 15;
                cp_async16(Ebase + nxt * EBUFB + (row * LDH + c16 * 8) * 2,
                           gE + ((size_t)row * LQQ + c16 * 8) * 2);
            }
#pragma unroll
            for (int l = 0; l < 2; l++) {
                int u = t + l * 256, row = u >> 3, c8 = u & 7;
                cp_async16(Cbase + nxt * CBUFB + (row * LDHC + c8 * 8) * 2,
                           gC + ((size_t)row * DDIM + c8 * 8) * 2);
            }
            cp_commit();
            cp_wait<1>();
        } else {
            cp_wait<0>();
        }
        __syncthreads();
#pragma unroll
        for (int ks = 0; ks < 4; ks++) {
            int ibase = kc * 64 + ks * 16;
            __half2 cm_lo = *(__half2*)&cmf_s[ibase + (lane & 3) * 2];
            __half2 cm_hi = *(__half2*)&cmf_s[ibase + 8 + (lane & 3) * 2];
            unsigned A[2][4];
            ldsm_x4t(aB + buf * EBUFB + ks * (16 * LDH * 2),      A[0][0], A[0][1], A[0][2], A[0][3]);
            ldsm_x4t(aB + buf * EBUFB + ks * (16 * LDH * 2) + 32, A[1][0], A[1][1], A[1][2], A[1][3]);
#pragma unroll
            for (int a = 0; a < 2; a++) {
                A[a][0] = hmul2u(A[a][0], cm_lo);
                A[a][1] = hmul2u(A[a][1], cm_lo);
                A[a][2] = hmul2u(A[a][2], cm_hi);
                A[a][3] = hmul2u(A[a][3], cm_hi);
            }
            unsigned Bf[4][2];
#pragma unroll
            for (int np = 0; np < 2; np++) {
                unsigned r0, r1, r2, r3;
                ldsm_x4t(bB + buf * CBUFB + ks * (16 * LDHC * 2) + np * 32, r0, r1, r2, r3);
                Bf[2 * np][0] = r0; Bf[2 * np][1] = r1;
                Bf[2 * np + 1][0] = r2; Bf[2 * np + 1][1] = r3;
            }
#pragma unroll
            for (int a = 0; a < 2; a++)
#pragma unroll
                for (int c = 0; c < 4; c++)
                    mma16816(acc[a][c][0], acc[a][c][1], acc[a][c][2], acc[a][c][3],
                             A[a][0], A[a][1], A[a][2], A[a][3], Bf[c][0], Bf[c][1]);
        }
        __syncthreads();
    }

    int g = lane >> 2, q4 = lane & 3;
#pragma unroll
    for (int a = 0; a < 2; a++) {
        int j0 = wm * 32 + a * 16 + g;
        float f0 = f_s[j0], f1 = f_s[j0 + 8];
        __half* o0 = g_Tm + ((size_t)(b * LQQ + j0)) * DDIM + d0;
        __half* o1 = o0 + 8 * DDIM;
#pragma unroll
        for (int c = 0; c < 4; c++) {
            int col = wn * 32 + c * 8 + 2 * q4;
            *(__half2*)(o0 + col) = __floats2half2_rn(acc[a][c][0] * f0, acc[a][c][1] * f0);
            *(__half2*)(o1 + col) = __floats2half2_rn(acc[a][c][2] * f1, acc[a][c][3] * f1);
        }
    }
}

// ---------------------------------------------------------------------------
// K4: fused dual GEMM A = (E·qmh)/z1, Batt = (E·Tm)/z1; parallel smem-staged
// epilogue, fully-coalesced float4 stores of [c, A, c*A, c*Batt].
// Grid (32, BB): bx&1 = d-half, bx>>1 = i-tile of 64. M=64 i, N=64 d, K=128 j.
// 3 CTAs/SM (reg cap 85) — R6-proven configuration.
// ---------------------------------------------------------------------------
__global__ __launch_bounds__(256, 3) void k4_out(const float* __restrict__ c_rep,
                                                 float* __restrict__ out) {
    int b = blockIdx.y;
    int i0 = (blockIdx.x >> 1) * 64;
    int d0 = (blockIdx.x & 1) * 64;
    extern __shared__ __half sm4[];
    __half* E_s = sm4;                   // [64][LDH]    rows i, cols j (A)
    __half* q_s = sm4 + 64 * LDH;        // [128][LDHC]  rows j, d-half (B)
    __half* t_s = q_s + 128 * LDHC;      // [128][LDHC]  rows j, d-half (B)
    float* Asm = (float*)sm4;            // staging (reused post-MMA): [64][LDS4]
    float* Bsm = Asm + 64 * LDS4;
    int t = threadIdx.x, lane = t & 31, wp = t >> 5, wm = wp >> 1, wn = wp & 1;
    const uint4* gE = (const uint4*)(g_Eh + ((size_t)(b * LCC + i0)) * LQQ);
    const __half* gQ = g_qmh + (size_t)b * LQQ * DDIM + d0;
    const __half* gT = g_Tm + (size_t)b * LQQ * DDIM + d0;
#pragma unroll
    for (int l = 0; l < 4; l++) {
        int u = t + l * 256, row = u >> 4, c16 = u & 15;
        *(uint4*)&E_s[row * LDH + c16 * 8] = gE[u];
    }
#pragma unroll
    for (int l = 0; l < 4; l++) {
        int u = t + l * 256, row = u >> 3, c8 = u & 7;
        *(uint4*)&q_s[row * LDHC + c8 * 8] = *(const uint4*)(gQ + (size_t)row * DDIM + c8 * 8);
        *(uint4*)&t_s[row * LDHC + c8 * 8] = *(const uint4*)(gT + (size_t)row * DDIM + c8 * 8);
    }
    __syncthreads();

    float accA[4][4], accB[4][4];
#pragma unroll
    for (int c = 0; c < 4; c++)
#pragma unroll
        for (int k = 0; k < 4; k++) { accA[c][k] = 0.f; accB[c][k] = 0.f; }

    unsigned aB = sm_addr(&E_s[(wm * 16 + (lane & 15)) * LDH + 8 * (lane >> 4)]);
    unsigned qB = sm_addr(&q_s[((lane & 7) + 8 * ((lane >> 3) & 1)) * LDHC
                               + wn * 32 + 8 * ((lane >> 4) & 1)]);
    unsigned tB = sm_addr(&t_s[((lane & 7) + 8 * ((lane >> 3) & 1)) * LDHC
                               + wn * 32 + 8 * ((lane >> 4) & 1)]);
#pragma unroll
    for (int ks = 0; ks < 8; ks++) {
        unsigned A0, A1, A2, A3;
        ldsm_x4(aB + ks * 32, A0, A1, A2, A3);
#pragma unroll
        for (int np = 0; np < 2; np++) {
            unsigned r0, r1, r2, r3;
            ldsm_x4t(qB + ks * (16 * LDHC * 2) + np * 32, r0, r1, r2, r3);
            mma16816(accA[2 * np][0], accA[2 * np][1], accA[2 * np][2], accA[2 * np][3],
                     A0, A1, A2, A3, r0, r1);
            mma16816(accA[2 * np + 1][0], accA[2 * np + 1][1], accA[2 * np + 1][2], accA[2 * np + 1][3],
                     A0, A1, A2, A3, r2, r3);
            ldsm_x4t(tB + ks * (16 * LDHC * 2) + np * 32, r0, r1, r2, r3);
            mma16816(accB[2 * np][0], accB[2 * np][1], accB[2 * np][2], accB[2 * np][3],
                     A0, A1, A2, A3, r0, r1);
            mma16816(accB[2 * np + 1][0], accB[2 * np + 1][1], accB[2 * np + 1][2], accB[2 * np + 1][3],
                     A0, A1, A2, A3, r2, r3);
        }
    }

    int g = lane >> 2, q4 = lane & 3;
    float z0, z1v;
    {
        size_t gr = (size_t)(b * LCC + i0 + wm * 16 + g);
        z0 = g_z1inv[gr];
        z1v = g_z1inv[gr + 8];
    }
    __syncthreads();   // all warps done reading E_s/q_s/t_s; smem reused below

    // all-warp parallel staging of 64 rows
    {
        int r0 = wm * 16 + g, r1 = r0 + 8;
#pragma unroll
        for (int c = 0; c < 4; c++) {
            int col = wn * 32 + c * 8 + 2 * q4;
            *(float2*)&Asm[r0 * LDS4 + col] = make_float2(accA[c][0] * z0, accA[c][1] * z0);
            *(float2*)&Asm[r1 * LDS4 + col] = make_float2(accA[c][2] * z1v, accA[c][3] * z1v);
            *(float2*)&Bsm[r0 * LDS4 + col] = make_float2(accB[c][0] * z0, accB[c][1] * z0);
            *(float2*)&Bsm[r1 * LDS4 + col] = make_float2(accB[c][2] * z1v, accB[c][3] * z1v);
        }
    }
    __syncthreads();

    // dense float4 stores: 64 rows x 64 cols, 4 iterations
#pragma unroll
    for (int it = 0; it < 4; it++) {
        int u = t + it * 256;
        int row = u >> 4, col = (u & 15) * 4;
        size_t gr = (size_t)(b * LCC + i0 + row);
        float4 c4 = *(const float4*)(c_rep + gr * DDIM + d0 + col);
        float4 a4 = *(const float4*)&Asm[row * LDS4 + col];
        float4 b4 = *(const float4*)&Bsm[row * LDS4 + col];
        float* ob = out + gr * (4 * DDIM) + d0 + col;
        *(float4*)ob = c4;
        *(float4*)(ob + DDIM) = a4;
        *(float4*)(ob + 2 * DDIM) = make_float4(c4.x * a4.x, c4.y * a4.y, c4.z * a4.z, c4.w * a4.w);
        *(float4*)(ob + 3 * DDIM) = make_float4(c4.x * b4.x, c4.y * b4.y, c4.z * b4.z, c4.w * b4.w);
    }
}

// ---------------------------------------------------------------------------
extern "C" void kernel_launch(void* const* d_in, const int* in_sizes, int n_in,
                              void* d_out, int out_size) {
    const float* c_rep  = (const float*)d_in[0];
    const float* q_rep  = (const float*)d_in[1];
    const int*   c_mask = (const int*)d_in[2];
    const int*   q_mask = (const int*)d_in[3];
    const float* w      = (const float*)d_in[4];
    float* out = (float*)d_out;

    k0_qprep<<<(BB * LQQ) / 8, 256>>>(q_rep, q_mask, w);
    {
        int smem = 2 * 128 * LDH * 2;  // 69632
        cudaFuncSetAttribute(k2_SE, cudaFuncAttributeMaxDynamicSharedMemorySize, smem);
        dim3 gr(8, BB);
        k2_SE<<<gr, 256, smem>>>(c_rep, c_mask, q_mask, w);
    }
    {
        int smem = 2 * EBUFB + 2 * CBUFB + 1024 * 2 + 128 * 4;  // 55808
        cudaFuncSetAttribute(k3_T, cudaFuncAttributeMaxDynamicSharedMemorySize, smem);
        dim3 gr(2, BB);
        k3_T<<<gr, 256, smem>>>(c_mask, q_mask);
    }
    {
        int smem = (64 * LDH + 2 * 128 * LDHC) * 2;  // 54272 (>= staging 36864)
        cudaFuncSetAttribute(k4_out, cudaFuncAttributeMaxDynamicSharedMemorySize, smem);
        dim3 gr(32, BB);
        k4_out<<<gr, 256, smem>>>(c_rep, out);
    }
}

// round 13
// speedup vs baseline: 1.1297x; 1.0004x over previous
#include <cuda_runtime.h>
#include <cuda_fp16.h>
#include <math.h>

#define BB 64
#define LCC 1024
#define LQQ 128
#define DDIM 128
#define LDH 136        // smem row stride in halfs (272B)
#define LDHC 72        // half-width slab row stride in halfs (144B)
#define LDS4 72        // k4 staging stride in floats
#define LOG2E 1.4426950408889634f

// ---- device scratch (allocation-free) ----
__device__ __half g_ch [(size_t)BB * LCC * DDIM];  // fp16(c)   (written by k2)
__device__ __half g_qwh[BB * LQQ * DDIM];          // fp16(q * w3 * log2e)
__device__ __half g_qmh[BB * LQQ * DDIM];          // fp16(q * qmf)
__device__ __half g_Eh [(size_t)BB * LCC * LQQ];   // fp16(exp(S))
__device__ __half g_Tm [BB * LQQ * DDIM];          // fp16(T * qmf)
__device__ float  g_qw2[BB * LQQ];                 // (q·w2) * log2e
__device__ float  g_z1inv[BB * LCC];
__device__ float  g_z2p[8][BB * LQQ];              // col-sum partials per i-tile

// ---- mma / ldmatrix / cp.async helpers ----
__device__ __forceinline__ unsigned sm_addr(const void* p) {
    return (unsigned)__cvta_generic_to_shared(p);
}
__device__ __forceinline__ void ldsm_x4(unsigned a, unsigned& r0, unsigned& r1,
                                        unsigned& r2, unsigned& r3) {
    asm volatile("ldmatrix.sync.aligned.m8n8.x4.shared.b16 {%0,%1,%2,%3}, [%4];"
                 : "=r"(r0), "=r"(r1), "=r"(r2), "=r"(r3) : "r"(a));
}
__device__ __forceinline__ void ldsm_x4t(unsigned a, unsigned& r0, unsigned& r1,
                                         unsigned& r2, unsigned& r3) {
    asm volatile("ldmatrix.sync.aligned.m8n8.x4.trans.shared.b16 {%0,%1,%2,%3}, [%4];"
                 : "=r"(r0), "=r"(r1), "=r"(r2), "=r"(r3) : "r"(a));
}
__device__ __forceinline__ void mma16816(float& c0, float& c1, float& c2, float& c3,
                                         unsigned a0, unsigned a1, unsigned a2, unsigned a3,
                                         unsigned b0, unsigned b1) {
    asm volatile(
        "mma.sync.aligned.m16n8k16.row.col.f32.f16.f16.f32 "
        "{%0,%1,%2,%3}, {%4,%5,%6,%7}, {%8,%9}, {%0,%1,%2,%3};"
        : "+f"(c0), "+f"(c1), "+f"(c2), "+f"(c3)
        : "r"(a0), "r"(a1), "r"(a2), "r"(a3), "r"(b0), "r"(b1));
}
__device__ __forceinline__ void cp_async16(unsigned saddr, const void* g) {
    asm volatile("cp.async.cg.shared.global [%0], [%1], 16;" :: "r"(saddr), "l"(g));
}
__device__ __forceinline__ void cp_commit() {
    asm volatile("cp.async.commit_group;");
}
template <int N> __device__ __forceinline__ void cp_wait() {
    asm volatile("cp.async.wait_group %0;" :: "n"(N));
}
__device__ __forceinline__ unsigned hmul2u(unsigned a, __half2 s) {
    __half2 r = __hmul2(*(__half2*)&a, s);
    return *(unsigned*)&r;
}

// ---------------------------------------------------------------------------
// K0: q-side prep only (8192 rows). Warp per row: qw2 fp32 dot (xlog2e),
// fp16 q*w3*log2e and q*qmf.
// ---------------------------------------------------------------------------
__global__ __launch_bounds__(256) void k0_qprep(const float* __restrict__ q_rep,
                                                const int* __restrict__ q_mask,
                                                const float* __restrict__ w) {
    int r    = (blockIdx.x * 256 + threadIdx.x) >> 5;
    int lane = threadIdx.x & 31;
    if (r >= BB * LQQ) return;
    float4 qv = *(const float4*)(q_rep + (size_t)r * DDIM + lane * 4);
    float4 w2 = *(const float4*)(w + DDIM + lane * 4);
    float4 w3 = *(const float4*)(w + 2 * DDIM + lane * 4);
    float s = qv.x * w2.x + qv.y * w2.y + qv.z * w2.z + qv.w * w2.w;
#pragma unroll
    for (int o = 16; o > 0; o >>= 1) s += __shfl_xor_sync(~0u, s, o);
    if (lane == 0) g_qw2[r] = s * LOG2E;
    __half2 a0 = __floats2half2_rn(qv.x * w3.x * LOG2E, qv.y * w3.y * LOG2E);
    __half2 a1 = __floats2half2_rn(qv.z * w3.z * LOG2E, qv.w * w3.w * LOG2E);
    uint2 u; u.x = *(unsigned*)&a0; u.y = *(unsigned*)&a1;
    *(uint2*)(g_qwh + (size_t)r * DDIM + lane * 4) = u;
    float mf = q_mask[r] ? 0.f : 1.f;
    __half2 m0 = __floats2half2_rn(qv.x * mf, qv.y * mf);
    __half2 m1 = __floats2half2_rn(qv.z * mf, qv.w * mf);
    uint2 v; v.x = *(unsigned*)&m0; v.y = *(unsigned*)&m1;
    *(uint2*)(g_qmh + (size_t)r * DDIM + lane * 4) = v;
}

// ---------------------------------------------------------------------------
// K2: fp32 c tile -> fp16 (smem + g_ch), cw1 in-register, MMA, then epilogue
// stages E through the dead q_s slab and writes g_Eh with DENSE uint4 stores.
// ---------------------------------------------------------------------------
__global__ __launch_bounds__(256) void k2_SE(const float* __restrict__ c_rep,
                                             const int* __restrict__ c_mask,
                                             const int* __restrict__ q_mask,
                                             const float* __restrict__ w) {
    int b = blockIdx.y, i0 = blockIdx.x * 128;
    extern __shared__ __half sm2[];
    __half* cw_s = sm2;                // [128][LDH]  A: rows i, cols d (fp16 c)
    __half* q_s  = sm2 + 128 * LDH;    // [128][LDH]  B: rows j, cols d; E staging after MMA
    __shared__ float z1s[128][2];
    __shared__ float z2s[128][4];
    __shared__ float qmf_s[128], cmf_s[128];
    __shared__ float cw1_s[128], qw2_s[128];
    int t = threadIdx.x, lane = t & 31, wp = t >> 5, wm = wp >> 1, wn = wp & 1;

    // phase 1a: fp32 c tile -> fp16 (smem + g_ch); cw1 from registers.
    const float4* gc4 = (const float4*)(c_rep + ((size_t)(b * LCC + i0)) * DDIM);
    uint2* gch2 = (uint2*)(g_ch + ((size_t)(b * LCC + i0)) * DDIM);
    float4 w1c = *(const float4*)(w + lane * 4);
#pragma unroll
    for (int l = 0; l < 16; l++) {
        int idx = t + l * 256;            // 0..4095 = 128 rows x 32 float4
        int row = wp + 8 * l;
        float4 v = gc4[idx];
        __half2 h0 = __floats2half2_rn(v.x, v.y);
        __half2 h1 = __floats2half2_rn(v.z, v.w);
        uint2 u; u.x = *(unsigned*)&h0; u.y = *(unsigned*)&h1;
        *(uint2*)&cw_s[row * LDH + lane * 4] = u;
        gch2[idx] = u;
        float s = v.x * w1c.x + v.y * w1c.y + v.z * w1c.z + v.w * w1c.w;
#pragma unroll
        for (int o = 16; o > 0; o >>= 1) s += __shfl_xor_sync(~0u, s, o);
        if (lane == 0) cw1_s[row] = s * LOG2E;
    }
    // phase 1b: q slab copy: 2048 uint4 (128 rows x 16 uint4)
    const uint4* gq = (const uint4*)(g_qwh + (size_t)b * LQQ * DDIM);
#pragma unroll
    for (int l = 0; l < 8; l++) {
        int idx = t + l * 256;
        int qrow = idx >> 4, c16 = idx & 15;
        *(uint4*)&q_s[qrow * LDH + c16 * 8] = gq[idx];
    }
    if (t < 128) {
        qmf_s[t] = q_mask[b * LQQ + t] ? 0.f : 1.f;
        cmf_s[t] = c_mask[b * LCC + i0 + t] ? 0.f : 1.f;
        qw2_s[t] = g_qw2[b * LQQ + t];
    }
    __syncthreads();

    float acc[2][8][4];
#pragma unroll
    for (int a = 0; a < 2; a++)
#pragma unroll
        for (int c = 0; c < 8; c++)
#pragma unroll
            for (int k = 0; k < 4; k++) acc[a][c][k] = 0.f;

    unsigned aB = sm_addr(&cw_s[(wm * 32 + (lane & 15)) * LDH + 8 * (lane >> 4)]);
    unsigned bB = sm_addr(&q_s[(wn * 64 + 8 * ((lane >> 4) & 1) + (lane & 7)) * LDH
                               + 8 * ((lane >> 3) & 1)]);
#pragma unroll
    for (int ks = 0; ks < 8; ks++) {
        unsigned A[2][4];
        ldsm_x4(aB + ks * 32,                 A[0][0], A[0][1], A[0][2], A[0][3]);
        ldsm_x4(aB + 16 * LDH * 2 + ks * 32,  A[1][0], A[1][1], A[1][2], A[1][3]);
        unsigned Bf[8][2];
#pragma unroll
        for (int np = 0; np < 4; np++) {
            unsigned r0, r1, r2, r3;
            ldsm_x4(bB + np * (16 * LDH * 2) + ks * 32, r0, r1, r2, r3);
            Bf[2 * np][0] = r0; Bf[2 * np][1] = r1;
            Bf[2 * np + 1][0] = r2; Bf[2 * np + 1][1] = r3;
        }
#pragma unroll
        for (int a = 0; a < 2; a++)
#pragma unroll
            for (int c = 0; c < 8; c++)
                mma16816(acc[a][c][0], acc[a][c][1], acc[a][c][2], acc[a][c][3],
                         A[a][0], A[a][1], A[a][2], A[a][3], Bf[c][0], Bf[c][1]);
    }
    __syncthreads();   // all warps done with q_s/cw_s ldsm; q_s becomes E staging

    // epilogue: rank-1 terms (log2 domain), ex2.f16x2, E -> q_s staging, z1/z2
    int g = lane >> 2, q4 = lane & 3;
    float z1a[2][2] = {{0.f, 0.f}, {0.f, 0.f}};
    float z2a[8][2];
#pragma unroll
    for (int c = 0; c < 8; c++) { z2a[c][0] = 0.f; z2a[c][1] = 0.f; }
#pragma unroll
    for (int a = 0; a < 2; a++) {
        int lr0 = wm * 32 + a * 16 + g;
        float cwv0 = cw1_s[lr0], cwv1 = cw1_s[lr0 + 8];
        float cmf0 = cmf_s[lr0], cmf1 = cmf_s[lr0 + 8];
#pragma unroll
        for (int c = 0; c < 8; c++) {
            int col = wn * 64 + c * 8 + 2 * q4;
            float qw0 = qw2_s[col], qw1 = qw2_s[col + 1];
            float qf0 = qmf_s[col], qf1 = qmf_s[col + 1];
            __half2 p01 = __floats2half2_rn(acc[a][c][0] + cwv0 + qw0,
                                            acc[a][c][1] + cwv0 + qw1);
            __half2 p23 = __floats2half2_rn(acc[a][c][2] + cwv1 + qw0,
                                            acc[a][c][3] + cwv1 + qw1);
            __half2 e01 = h2exp2(p01);
            __half2 e23 = h2exp2(p23);
            *(__half2*)&q_s[lr0 * LDH + col] = e01;          // bank-conflict-free
            *(__half2*)&q_s[(lr0 + 8) * LDH + col] = e23;
            float2 f01 = __half22float2(e01);
            float2 f23 = __half22float2(e23);
            z1a[a][0] += qf0 * f01.x + qf1 * f01.y;
            z1a[a][1] += qf0 * f23.x + qf1 * f23.y;
            z2a[c][0] += cmf0 * f01.x + cmf1 * f23.x;
            z2a[c][1] += cmf0 * f01.y + cmf1 * f23.y;
        }
    }
#pragma unroll
    for (int a = 0; a < 2; a++)
#pragma unroll
        for (int h = 0; h < 2; h++) {
            float v = z1a[a][h];
            v += __shfl_xor_sync(~0u, v, 1);
            v += __shfl_xor_sync(~0u, v, 2);
            if (q4 == 0) z1s[wm * 32 + a * 16 + g + 8 * h][wn] = v;
        }
#pragma unroll
    for (int c = 0; c < 8; c++)
#pragma unroll
        for (int s = 0; s < 2; s++) {
            float v = z2a[c][s];
            v += __shfl_xor_sync(~0u, v, 4);
            v += __shfl_xor_sync(~0u, v, 8);
            v += __shfl_xor_sync(~0u, v, 16);
            if (g == 0) z2s[wn * 64 + c * 8 + 2 * q4 + s][wm] = v;
        }
    __syncthreads();

    // dense E write-out: 2048 uint4 (128 rows x 16)
    uint4* gEo = (uint4*)(g_Eh + ((size_t)(b * LCC + i0)) * LQQ);
#pragma unroll
    for (int l = 0; l < 8; l++) {
        int idx = t + l * 256;
        int row = idx >> 4, c16 = idx & 15;
        gEo[idx] = *(uint4*)&q_s[row * LDH + c16 * 8];
    }
    if (t < 128) {
        g_z1inv[b * LCC + i0 + t] = 1.f / (z1s[t][0] + z1s[t][1]);
        g_z2p[blockIdx.x][b * LQQ + t] = z2s[t][0] + z2s[t][1] + z2s[t][2] + z2s[t][3];
    }
}

// ---------------------------------------------------------------------------
// K3: T[j,d] = qmf[j]/z2[j] * sum_i cmf[i]*E[i,j]*c[i,d]  -> fp16 g_Tm
// N-split over d halves: grid (2, BB). M=128 j, N=64 d, K=1024 i.
// ---------------------------------------------------------------------------
#define EBUFB (64 * LDH * 2)    // bytes per E buffer
#define CBUFB (64 * LDHC * 2)   // bytes per c buffer
__global__ __launch_bounds__(256) void k3_T(const int* __restrict__ c_mask,
                                            const int* __restrict__ q_mask) {
    int b = blockIdx.y, d0 = blockIdx.x * 64;
    extern __shared__ __half s3[];
    __half* E_s   = s3;                         // 2 x 64 x LDH
    __half* c_s   = s3 + 2 * 64 * LDH;          // 2 x 64 x LDHC
    __half* cmf_s = s3 + 2 * 64 * LDH + 2 * 64 * LDHC;  // 1024
    float*  f_s   = (float*)(cmf_s + 1024);     // 128
    int t = threadIdx.x, lane = t & 31, wp = t >> 5, wm = wp >> 1, wn = wp & 1;

    unsigned Ebase = sm_addr(E_s);
    unsigned Cbase = sm_addr(c_s);
    {
        const char* gE = (const char*)(g_Eh + ((size_t)b * LCC) * LQQ);
        const char* gC = (const char*)(g_ch + ((size_t)b * LCC) * DDIM + d0);
#pragma unroll
        for (int l = 0; l < 4; l++) {
            int u = t + l * 256, row = u >> 4, c16 = u & 15;
            cp_async16(Ebase + (row * LDH + c16 * 8) * 2, gE + ((size_t)row * LQQ + c16 * 8) * 2);
        }
#pragma unroll
        for (int l = 0; l < 2; l++) {
            int u = t + l * 256, row = u >> 3, c8 = u & 7;
            cp_async16(Cbase + (row * LDHC + c8 * 8) * 2, gC + ((size_t)row * DDIM + c8 * 8) * 2);
        }
        cp_commit();
    }
#pragma unroll
    for (int l = 0; l < 4; l++) {
        int i = t + l * 256;
        cmf_s[i] = __float2half(c_mask[b * LCC + i] ? 0.f : 1.f);
    }
    if (t < 128) {
        float z2 = 0.f;
#pragma unroll
        for (int s = 0; s < 8; s++) z2 += g_z2p[s][b * LQQ + t];
        f_s[t] = q_mask[b * LQQ + t] ? 0.f : (1.f / z2);
    }

    float acc[2][4][4];
#pragma unroll
    for (int a = 0; a < 2; a++)
#pragma unroll
        for (int c = 0; c < 4; c++)
#pragma unroll
            for (int k = 0; k < 4; k++) acc[a][c][k] = 0.f;

    unsigned aB = Ebase + (((lane & 7) + 8 * ((lane >> 4) & 1)) * LDH
                           + wm * 32 + 8 * ((lane >> 3) & 1)) * 2;
    unsigned bB = Cbase + (((lane & 7) + 8 * ((lane >> 3) & 1)) * LDHC
                           + wn * 32 + 8 * ((lane >> 4) & 1)) * 2;

    for (int kc = 0; kc < 16; kc++) {
        int buf = kc & 1;
        if (kc + 1 < 16) {
            int nxt = buf ^ 1;
            const char* gE = (const char*)(g_Eh + ((size_t)(b * LCC + (kc + 1) * 64)) * LQQ);
            const char* gC = (const char*)(g_ch + ((size_t)(b * LCC + (kc + 1) * 64)) * DDIM + d0);
#pragma unroll
            for (int l = 0; l < 4; l++) {
                int u = t + l * 256, row = u >> 4, c16 = u & 15;
                cp_async16(Ebase + nxt * EBUFB + (row * LDH + c16 * 8) * 2,
                           gE + ((size_t)row * LQQ + c16 * 8) * 2);
            }
#pragma unroll
            for (int l = 0; l < 2; l++) {
                int u = t + l * 256, row = u >> 3, c8 = u & 7;
                cp_async16(Cbase + nxt * CBUFB + (row * LDHC + c8 * 8) * 2,
                           gC + ((size_t)row * DDIM + c8 * 8) * 2);
            }
            cp_commit();
            cp_wait<1>();
        } else {
            cp_wait<0>();
        }
        __syncthreads();
#pragma unroll
        for (int ks = 0; ks < 4; ks++) {
            int ibase = kc * 64 + ks * 16;
            __half2 cm_lo = *(__half2*)&cmf_s[ibase + (lane & 3) * 2];
            __half2 cm_hi = *(__half2*)&cmf_s[ibase + 8 + (lane & 3) * 2];
            unsigned A[2][4];
            ldsm_x4t(aB + buf * EBUFB + ks * (16 * LDH * 2),      A[0][0], A[0][1], A[0][2], A[0][3]);
            ldsm_x4t(aB + buf * EBUFB + ks * (16 * LDH * 2) + 32, A[1][0], A[1][1], A[1][2], A[1][3]);
#pragma unroll
            for (int a = 0; a < 2; a++) {
                A[a][0] = hmul2u(A[a][0], cm_lo);
                A[a][1] = hmul2u(A[a][1], cm_lo);
                A[a][2] = hmul2u(A[a][2], cm_hi);
                A[a][3] = hmul2u(A[a][3], cm_hi);
            }
            unsigned Bf[4][2];
#pragma unroll
            for (int np = 0; np < 2; np++) {
                unsigned r0, r1, r2, r3;
                ldsm_x4t(bB + buf * CBUFB + ks * (16 * LDHC * 2) + np * 32, r0, r1, r2, r3);
                Bf[2 * np][0] = r0; Bf[2 * np][1] = r1;
                Bf[2 * np + 1][0] = r2; Bf[2 * np + 1][1] = r3;
            }
#pragma unroll
            for (int a = 0; a < 2; a++)
#pragma unroll
                for (int c = 0; c < 4; c++)
                    mma16816(acc[a][c][0], acc[a][c][1], acc[a][c][2], acc[a][c][3],
                             A[a][0], A[a][1], A[a][2], A[a][3], Bf[c][0], Bf[c][1]);
        }
        __syncthreads();
    }

    int g = lane >> 2, q4 = lane & 3;
#pragma unroll
    for (int a = 0; a < 2; a++) {
        int j0 = wm * 32 + a * 16 + g;
        float f0 = f_s[j0], f1 = f_s[j0 + 8];
        __half* o0 = g_Tm + ((size_t)(b * LQQ + j0)) * DDIM + d0;
        __half* o1 = o0 + 8 * DDIM;
#pragma unroll
        for (int c = 0; c < 4; c++) {
            int col = wn * 32 + c * 8 + 2 * q4;
            *(__half2*)(o0 + col) = __floats2half2_rn(acc[a][c][0] * f0, acc[a][c][1] * f0);
            *(__half2*)(o1 + col) = __floats2half2_rn(acc[a][c][2] * f1, acc[a][c][3] * f1);
        }
    }
}

// ---------------------------------------------------------------------------
// K4: fused dual GEMM A = (E·qmh)/z1, Batt = (E·Tm)/z1; parallel smem-staged
// epilogue, fully-coalesced float4 stores of [c, A, c*A, c*Batt].
// Grid (32, BB): bx&1 = d-half, bx>>1 = i-tile of 64. M=64 i, N=64 d, K=128 j.
// 3 CTAs/SM (reg cap 85) — R6-proven configuration.
// ---------------------------------------------------------------------------
__global__ __launch_bounds__(256, 3) void k4_out(const float* __restrict__ c_rep,
                                                 float* __restrict__ out) {
    int b = blockIdx.y;
    int i0 = (blockIdx.x >> 1) * 64;
    int d0 = (blockIdx.x & 1) * 64;
    extern __shared__ __half sm4[];
    __half* E_s = sm4;                   // [64][LDH]    rows i, cols j (A)
    __half* q_s = sm4 + 64 * LDH;        // [128][LDHC]  rows j, d-half (B)
    __half* t_s = q_s + 128 * LDHC;      // [128][LDHC]  rows j, d-half (B)
    float* Asm = (float*)sm4;            // staging (reused post-MMA): [64][LDS4]
    float* Bsm = Asm + 64 * LDS4;
    int t = threadIdx.x, lane = t & 31, wp = t >> 5, wm = wp >> 1, wn = wp & 1;
    const uint4* gE = (const uint4*)(g_Eh + ((size_t)(b * LCC + i0)) * LQQ);
    const __half* gQ = g_qmh + (size_t)b * LQQ * DDIM + d0;
    const __half* gT = g_Tm + (size_t)b * LQQ * DDIM + d0;
#pragma unroll
    for (int l = 0; l < 4; l++) {
        int u = t + l * 256, row = u >> 4, c16 = u & 15;
        *(uint4*)&E_s[row * LDH + c16 * 8] = gE[u];
    }
#pragma unroll
    for (int l = 0; l < 4; l++) {
        int u = t + l * 256, row = u >> 3, c8 = u & 7;
        *(uint4*)&q_s[row * LDHC + c8 * 8] = *(const uint4*)(gQ + (size_t)row * DDIM + c8 * 8);
        *(uint4*)&t_s[row * LDHC + c8 * 8] = *(const uint4*)(gT + (size_t)row * DDIM + c8 * 8);
    }
    __syncthreads();

    float accA[4][4], accB[4][4];
#pragma unroll
    for (int c = 0; c < 4; c++)
#pragma unroll
        for (int k = 0; k < 4; k++) { accA[c][k] = 0.f; accB[c][k] = 0.f; }

    unsigned aB = sm_addr(&E_s[(wm * 16 + (lane & 15)) * LDH + 8 * (lane >> 4)]);
    unsigned qB = sm_addr(&q_s[((lane & 7) + 8 * ((lane >> 3) & 1)) * LDHC
                               + wn * 32 + 8 * ((lane >> 4) & 1)]);
    unsigned tB = sm_addr(&t_s[((lane & 7) + 8 * ((lane >> 3) & 1)) * LDHC
                               + wn * 32 + 8 * ((lane >> 4) & 1)]);
#pragma unroll
    for (int ks = 0; ks < 8; ks++) {
        unsigned A0, A1, A2, A3;
        ldsm_x4(aB + ks * 32, A0, A1, A2, A3);
#pragma unroll
        for (int np = 0; np < 2; np++) {
            unsigned r0, r1, r2, r3;
            ldsm_x4t(qB + ks * (16 * LDHC * 2) + np * 32, r0, r1, r2, r3);
            mma16816(accA[2 * np][0], accA[2 * np][1], accA[2 * np][2], accA[2 * np][3],
                     A0, A1, A2, A3, r0, r1);
            mma16816(accA[2 * np + 1][0], accA[2 * np + 1][1], accA[2 * np + 1][2], accA[2 * np + 1][3],
                     A0, A1, A2, A3, r2, r3);
            ldsm_x4t(tB + ks * (16 * LDHC * 2) + np * 32, r0, r1, r2, r3);
            mma16816(accB[2 * np][0], accB[2 * np][1], accB[2 * np][2], accB[2 * np][3],
                     A0, A1, A2, A3, r0, r1);
            mma16816(accB[2 * np + 1][0], accB[2 * np + 1][1], accB[2 * np + 1][2], accB[2 * np + 1][3],
                     A0, A1, A2, A3, r2, r3);
        }
    }

    int g = lane >> 2, q4 = lane & 3;
    float z0, z1v;
    {
        size_t gr = (size_t)(b * LCC + i0 + wm * 16 + g);
        z0 = g_z1inv[gr];
        z1v = g_z1inv[gr + 8];
    }
    __syncthreads();   // all warps done reading E_s/q_s/t_s; smem reused below

    // all-warp parallel staging of 64 rows
    {
        int r0 = wm * 16 + g, r1 = r0 + 8;
#pragma unroll
        for (int c = 0; c < 4; c++) {
            int col = wn * 32 + c * 8 + 2 * q4;
            *(float2*)&Asm[r0 * LDS4 + col] = make_float2(accA[c][0] * z0, accA[c][1] * z0);
            *(float2*)&Asm[r1 * LDS4 + col] = make_float2(accA[c][2] * z1v, accA[c][3] * z1v);
            *(float2*)&Bsm[r0 * LDS4 + col] = make_float2(accB[c][0] * z0, accB[c][1] * z0);
            *(float2*)&Bsm[r1 * LDS4 + col] = make_float2(accB[c][2] * z1v, accB[c][3] * z1v);
        }
    }
    __syncthreads();

    // dense float4 stores: 64 rows x 64 cols, 4 iterations
#pragma unroll
    for (int it = 0; it < 4; it++) {
        int u = t + it * 256;
        int row = u >> 4, col = (u & 15) * 4;
        size_t gr = (size_t)(b * LCC + i0 + row);
        float4 c4 = *(const float4*)(c_rep + gr * DDIM + d0 + col);
        float4 a4 = *(const float4*)&Asm[row * LDS4 + col];
        float4 b4 = *(const float4*)&Bsm[row * LDS4 + col];
        float* ob = out + gr * (4 * DDIM) + d0 + col;
        *(float4*)ob = c4;
        *(float4*)(ob + DDIM) = a4;
        *(float4*)(ob + 2 * DDIM) = make_float4(c4.x * a4.x, c4.y * a4.y, c4.z * a4.z, c4.w * a4.w);
        *(float4*)(ob + 3 * DDIM) = make_float4(c4.x * b4.x, c4.y * b4.y, c4.z * b4.z, c4.w * b4.w);
    }
}

// ---------------------------------------------------------------------------
extern "C" void kernel_launch(void* const* d_in, const int* in_sizes, int n_in,
                              void* d_out, int out_size) {
    const float* c_rep  = (const float*)d_in[0];
    const float* q_rep  = (const float*)d_in[1];
    const int*   c_mask = (const int*)d_in[2];
    const int*   q_mask = (const int*)d_in[3];
    const float* w      = (const float*)d_in[4];
    float* out = (float*)d_out;

    k0_qprep<<<(BB * LQQ) / 8, 256>>>(q_rep, q_mask, w);
    {
        int smem = 2 * 128 * LDH * 2;  // 69632
        cudaFuncSetAttribute(k2_SE, cudaFuncAttributeMaxDynamicSharedMemorySize, smem);
        dim3 gr(8, BB);
        k2_SE<<<gr, 256, smem>>>(c_rep, c_mask, q_mask, w);
    }
    {
        int smem = 2 * EBUFB + 2 * CBUFB + 1024 * 2 + 128 * 4;  // 55808
        cudaFuncSetAttribute(k3_T, cudaFuncAttributeMaxDynamicSharedMemorySize, smem);
        dim3 gr(2, BB);
        k3_T<<<gr, 256, smem>>>(c_mask, q_mask);
    }
    {
        int smem = (64 * LDH + 2 * 128 * LDHC) * 2;  // 54272 (>= staging 36864)
        cudaFuncSetAttribute(k4_out, cudaFuncAttributeMaxDynamicSharedMemorySize, smem);
        dim3 gr(32, BB);
        k4_out<<<gr, 256, smem>>>(c_rep, out);
    }
}